// round 13
// baseline (speedup 1.0000x reference)
#include <cuda_runtime.h>
#include <cuda_bf16.h>
#include <stdint.h>
#include <math.h>

#define N_NODES 10000
#define N_EDGES 320000
#define HID 128
#define NC0 10
#define NC1 5

// ---------------- device scratch ----------------
__device__ float g_deg[N_NODES];
__device__ int   g_cnt[N_NODES];
__device__ int   g_cur[N_NODES];
__device__ int   g_offs[N_NODES + 1];
__device__ int   g_srow[N_EDGES];
__device__ float g_sew[N_EDGES];
__device__ float g_hlin[N_NODES * HID];
__device__ float g_pre1[N_NODES * HID];
__device__ float g_pre2[N_NODES * HID];
__device__ float g_e1[N_NODES * HID];
__device__ float g_bottom[N_NODES * HID];
__device__ float g_stats1[2 * HID];
__device__ float g_stats2[2 * HID];
__device__ int   g_c0[N_NODES];
__device__ int   g_c1[NC0];
__device__ float g_xp0[NC0 * HID];
__device__ float g_A0[NC0 * NC0];
__device__ float g_latent0[NC0 * HID];
__device__ float g_latent1[NC1 * HID];
__device__ int   g_bar0;

// pre-converted transposed weights [N][K] bf16 hi/lo
#define WO_CONV1 0
#define WO_CONV2 16384
#define WO_ENC1  32768
#define WO_ENC2  81920
#define WO_FC1   98304
#define W_TOTAL  294912
__device__ __align__(16) __nv_bfloat16 g_wh[W_TOTAL];
__device__ __align__(16) __nv_bfloat16 g_wl[W_TOTAL];

// ---------------- PTX wrappers ----------------
__device__ __forceinline__ uint32_t smem_u32(const void* p) {
    uint32_t a;
    asm("{ .reg .u64 t; cvta.to.shared.u64 t, %1; cvt.u32.u64 %0, t; }" : "=r"(a) : "l"(p));
    return a;
}
__device__ __forceinline__ void ldsm4(uint32_t r[4], uint32_t addr) {
    asm volatile("ldmatrix.sync.aligned.m8n8.x4.shared.b16 {%0,%1,%2,%3}, [%4];"
        : "=r"(r[0]), "=r"(r[1]), "=r"(r[2]), "=r"(r[3]) : "r"(addr));
}
__device__ __forceinline__ void mma16816(float d[4], const uint32_t a[4], const uint32_t b[2]) {
    asm volatile("mma.sync.aligned.m16n8k16.row.col.f32.bf16.bf16.f32 "
        "{%0,%1,%2,%3}, {%4,%5,%6,%7}, {%8,%9}, {%0,%1,%2,%3};"
        : "+f"(d[0]), "+f"(d[1]), "+f"(d[2]), "+f"(d[3])
        : "r"(a[0]), "r"(a[1]), "r"(a[2]), "r"(a[3]), "r"(b[0]), "r"(b[1]));
}
__device__ __forceinline__ void cp16(uint32_t d, const void* s) {
    asm volatile("cp.async.cg.shared.global [%0], [%1], 16;" :: "r"(d), "l"(s));
}
#define CP_COMMIT() asm volatile("cp.async.commit_group;" ::: "memory")
#define CP_WAIT0()  asm volatile("cp.async.wait_group 0;" ::: "memory")

// row swizzle value: rows 0..7 -> 0,4,1,5,2,6,3,7 (distinct mod 8 over 8 rows;
// adjacent even/odd rows differ by 4 -> staging stores conflict-free too)
__device__ __forceinline__ uint32_t swv(int row) {
    int r = row & 7;
    return (uint32_t)(((r & 1) << 2) | (r >> 1));
}
// smem tile: 64 rows x 256B (128 bf16); chunk = 16B
__device__ __forceinline__ uint32_t tadr(int row, int ch) {
    return (uint32_t)(row * 256) + ((uint32_t)(ch ^ (int)swv(row)) << 4);
}

// ---------------- fused weight prep + state zeroing ----------------
__global__ void k_wz(const float* __restrict__ w1, const float* __restrict__ w2,
                     const float* __restrict__ we1, const float* __restrict__ we2,
                     const float* __restrict__ wf1, float* __restrict__ out) {
    int i = blockIdx.x * blockDim.x + threadIdx.x;
    if (i == 0) g_bar0 = 0;
    if (i < N_NODES) { g_deg[i] = 0.f; g_cnt[i] = 0; g_cur[i] = 0; out[i] = 0.f; }
    if (i < 2 * HID) { g_stats1[i] = 0.f; g_stats2[i] = 0.f; }
    if (i < NC0 * HID) g_xp0[i] = 0.f;
    if (i < NC0 * NC0) g_A0[i] = 0.f;
    if (i >= W_TOTAL) return;
    const float* w; int K, Nn; int d = i;
    if (d < 16384)       { w = w1;  K = 128; Nn = 128; }
    else if (d < 32768)  { w = w2;  K = 128; Nn = 128; d -= 16384; }
    else if (d < 81920)  { w = we1; K = 384; Nn = 128; d -= 32768; }
    else if (d < 98304)  { w = we2; K = 128; Nn = 128; d -= 81920; }
    else                 { w = wf1; K = 384; Nn = 512; d -= 98304; }
    int n = d / K, k = d % K;
    float v = w[(size_t)k * Nn + n];
    __nv_bfloat16 h = __float2bfloat16(v);
    float l = v - __bfloat162float(h);
    g_wh[i] = h;
    g_wl[i] = __float2bfloat16(l);
}

// ---------------- bf16x3 tensor-core GEMM, 64x64 tile, full-K staging ----------------
__global__ __launch_bounds__(256, 3)
void tgemm(const float* __restrict__ A0, const float* __restrict__ A1, const float* __restrict__ A2,
           const float* __restrict__ st0, const float* __restrict__ ga0, const float* __restrict__ be0,
           const float* __restrict__ st1, const float* __restrict__ ga1, const float* __restrict__ be1,
           const float* __restrict__ st2, const float* __restrict__ ga2, const float* __restrict__ be2,
           const __nv_bfloat16* __restrict__ Bh, const __nv_bfloat16* __restrict__ Bl,
           const float* __restrict__ bias, float* __restrict__ C,
           const float* __restrict__ w2, float* __restrict__ outAcc,
           int M, int nseg, int Ncols, int doRelu, int idxmode)
{
    extern __shared__ char dsm[];
    char* sAh = dsm;                  // 16 KB: A hi, 64 x 256B
    char* sAl = dsm + 16384;          // 16 KB: A lo
    char* sBh = dsm + 32768;          // 16 KB: B hi
    char* sBl = dsm + 49152;          // 16 KB: B lo
    uint32_t uAh = smem_u32(sAh), uAl = smem_u32(sAl);
    uint32_t uBh = smem_u32(sBh), uBl = smem_u32(sBl);

    int t = threadIdx.x;
    int wid = t >> 5, lane = t & 31;
    int wm = wid >> 1, wn = wid & 1;            // 4 x 2 warps, each 16 x 32
    int m0 = blockIdx.x * 64, n0 = blockIdx.y * 64;

    // staging: thread -> row t>>2, part t&3 owns chunks {p, p+4, p+8, p+12}
    int sRow = t >> 2, sPart = t & 3;
    int gm = m0 + sRow;
    bool mOK = gm < M;
    int gi = mOK ? gm : 0;
    int i1 = gi, i2 = gi;
    if (idxmode && mOK) { i1 = g_c0[gi]; i2 = g_c1[i1]; }
    const float* rp[3];
    rp[0] = A0 ? A0 + (size_t)gi * 128 : (const float*)0;
    rp[1] = A1 ? A1 + (size_t)i1 * 128 : (const float*)0;
    rp[2] = A2 ? A2 + (size_t)i2 * 128 : (const float*)0;
    const float* stp[3] = { st0, st1, st2 };
    const float* gap[3] = { ga0, ga1, ga2 };
    const float* bep[3] = { be0, be1, be2 };

    int Kfull = nseg * 128;
    const float invN = 1.0f / (float)N_NODES;

    // MMA-side precomputed addresses
    int mid = lane >> 3, r8 = lane & 7;
    int arow = wm * 16 + (mid & 1) * 8 + r8;
    int brow = wn * 32 + (mid >> 1) * 8 + r8;   // ntp=0; ntp=1 adds 16 (same swv)
    uint32_t sva = swv(arow), svb = swv(brow);
    uint32_t aH = uAh + arow * 256, aL = uAl + arow * 256;
    uint32_t bH0 = uBh + brow * 256, bL0 = uBl + brow * 256;
    uint32_t bH1 = bH0 + 16 * 256,  bL1 = bL0 + 16 * 256;

    float d[4][4];
    #pragma unroll
    for (int a = 0; a < 4; a++)
        #pragma unroll
        for (int b = 0; b < 4; b++) d[a][b] = 0.f;

    for (int seg = 0; seg < nseg; seg++) {
        if (seg) __syncthreads();   // previous MMA stretch done before overwrite
        // ---- stage B via cp.async ----
        {
            size_t gb = (size_t)(n0 + sRow) * Kfull + (size_t)seg * 128;
            #pragma unroll
            for (int j = 0; j < 4; j++) {
                int ch = sPart + 4 * j;
                uint32_t sw = tadr(sRow, ch);
                cp16(uBh + sw, Bh + gb + ch * 8);
                cp16(uBl + sw, Bl + gb + ch * 8);
            }
            CP_COMMIT();
        }
        // ---- stage A: load fp32, optional BN, hi/lo split ----
        {
            const float* ap = rp[seg];
            const float* st = stp[seg];
            const float* ga = gap[seg];
            const float* be = bep[seg];
            #pragma unroll
            for (int j = 0; j < 4; j++) {
                int ch = sPart + 4 * j;
                int kin = ch * 8;
                float4 v0 = mOK ? *(const float4*)(ap + kin)     : make_float4(0.f, 0.f, 0.f, 0.f);
                float4 v1 = mOK ? *(const float4*)(ap + kin + 4) : make_float4(0.f, 0.f, 0.f, 0.f);
                float f[8] = { v0.x, v0.y, v0.z, v0.w, v1.x, v1.y, v1.z, v1.w };
                if (st) {
                    #pragma unroll
                    for (int jj = 0; jj < 8; jj++) {
                        int k = kin + jj;
                        float m = st[k] * invN;
                        float var = st[HID + k] * invN - m * m;
                        float sc = ga[k] * rsqrtf(var + 1e-5f);
                        f[jj] = f[jj] * sc + (be[k] - m * sc);
                    }
                }
                uint32_t hi[4], lo[4];
                #pragma unroll
                for (int q = 0; q < 4; q++) {
                    __nv_bfloat162 h = __floats2bfloat162_rn(f[q * 2], f[q * 2 + 1]);
                    __nv_bfloat162 l = __floats2bfloat162_rn(f[q * 2] - __bfloat162float(h.x),
                                                             f[q * 2 + 1] - __bfloat162float(h.y));
                    hi[q] = *(uint32_t*)&h; lo[q] = *(uint32_t*)&l;
                }
                uint32_t sw = tadr(sRow, ch);
                *(uint4*)(sAh + sw) = make_uint4(hi[0], hi[1], hi[2], hi[3]);
                *(uint4*)(sAl + sw) = make_uint4(lo[0], lo[1], lo[2], lo[3]);
            }
        }
        CP_WAIT0();
        __syncthreads();

        // ---- uninterrupted MMA stretch over K=128 ----
        #pragma unroll
        for (int kk = 0; kk < 8; kk++) {
            int ach = 2 * kk + (mid >> 1);
            uint32_t aw = (uint32_t)(ach ^ (int)sva) << 4;
            uint32_t ah[4], al[4];
            ldsm4(ah, aH + aw);
            ldsm4(al, aL + aw);
            int bch = 2 * kk + (mid & 1);
            uint32_t bw = (uint32_t)(bch ^ (int)svb) << 4;
            uint32_t bh[4][2], bl[4][2], tmp[4];
            ldsm4(tmp, bH0 + bw);
            bh[0][0] = tmp[0]; bh[0][1] = tmp[1]; bh[1][0] = tmp[2]; bh[1][1] = tmp[3];
            ldsm4(tmp, bH1 + bw);
            bh[2][0] = tmp[0]; bh[2][1] = tmp[1]; bh[3][0] = tmp[2]; bh[3][1] = tmp[3];
            ldsm4(tmp, bL0 + bw);
            bl[0][0] = tmp[0]; bl[0][1] = tmp[1]; bl[1][0] = tmp[2]; bl[1][1] = tmp[3];
            ldsm4(tmp, bL1 + bw);
            bl[2][0] = tmp[0]; bl[2][1] = tmp[1]; bl[3][0] = tmp[2]; bl[3][1] = tmp[3];
            #pragma unroll
            for (int nt = 0; nt < 4; nt++) {
                mma16816(d[nt], ah, bh[nt]);
                mma16816(d[nt], ah, bl[nt]);
                mma16816(d[nt], al, bh[nt]);
            }
        }
    }

    // ---- epilogue ----
    int rq = lane >> 2, cq = (lane & 3) * 2;
    int grow0 = m0 + wm * 16 + rq;
    if (w2) {
        float p0 = 0.f, p1 = 0.f;
        #pragma unroll
        for (int nt = 0; nt < 4; nt++) {
            int gcol = n0 + wn * 32 + nt * 8 + cq;
            float2 bv = *(const float2*)(bias + gcol);
            float o0x = fmaxf(d[nt][0] + bv.x, 0.f), o0y = fmaxf(d[nt][1] + bv.y, 0.f);
            float o1x = fmaxf(d[nt][2] + bv.x, 0.f), o1y = fmaxf(d[nt][3] + bv.y, 0.f);
            float2 wv = *(const float2*)(w2 + gcol);
            p0 += o0x * wv.x + o0y * wv.y;
            p1 += o1x * wv.x + o1y * wv.y;
        }
        p0 += __shfl_xor_sync(0xffffffffu, p0, 1);
        p0 += __shfl_xor_sync(0xffffffffu, p0, 2);
        p1 += __shfl_xor_sync(0xffffffffu, p1, 1);
        p1 += __shfl_xor_sync(0xffffffffu, p1, 2);
        if ((lane & 3) == 0) {
            if (grow0 < M)     atomicAdd(&outAcc[grow0], p0);
            if (grow0 + 8 < M) atomicAdd(&outAcc[grow0 + 8], p1);
        }
    } else {
        #pragma unroll
        for (int nt = 0; nt < 4; nt++) {
            int gcol = n0 + wn * 32 + nt * 8 + cq;
            float2 bv = make_float2(0.f, 0.f);
            if (bias) bv = *(const float2*)(bias + gcol);
            float2 o0 = make_float2(d[nt][0] + bv.x, d[nt][1] + bv.y);
            float2 o1 = make_float2(d[nt][2] + bv.x, d[nt][3] + bv.y);
            if (doRelu) {
                o0.x = fmaxf(o0.x, 0.f); o0.y = fmaxf(o0.y, 0.f);
                o1.x = fmaxf(o1.x, 0.f); o1.y = fmaxf(o1.y, 0.f);
            }
            if (grow0 < M)     *(float2*)(C + (size_t)grow0 * Ncols + gcol) = o0;
            if (grow0 + 8 < M) *(float2*)(C + (size_t)(grow0 + 8) * Ncols + gcol) = o1;
        }
    }
}

// ---------------- edge infra ----------------
__global__ void k_count(const int* __restrict__ col, const float* __restrict__ ew) {
    int e = blockIdx.x * blockDim.x + threadIdx.x;
    if (e >= N_EDGES) return;
    int c = col[e];
    atomicAdd(&g_cnt[c], 1);
    atomicAdd(&g_deg[c], ew[e]);
}

__global__ void k_scan() {   // shuffle scan + fused dinv
    __shared__ int wsum[32];
    const int PER = 10;
    int t = threadIdx.x;
    int lane = t & 31, warp = t >> 5;
    int base = t * PER;
    int loc[PER];
    int s = 0;
    #pragma unroll
    for (int p = 0; p < PER; p++) {
        int idx = base + p;
        int v = 0;
        if (idx < N_NODES) {
            v = g_cnt[idx];
            g_deg[idx] = rsqrtf(g_deg[idx] + 1.0f);
        }
        loc[p] = s; s += v;
    }
    int inc = s;
    #pragma unroll
    for (int off = 1; off < 32; off <<= 1) {
        int n = __shfl_up_sync(0xffffffffu, inc, off);
        if (lane >= off) inc += n;
    }
    if (lane == 31) wsum[warp] = inc;
    __syncthreads();
    if (warp == 0) {
        int w = wsum[lane];
        #pragma unroll
        for (int off = 1; off < 32; off <<= 1) {
            int n = __shfl_up_sync(0xffffffffu, w, off);
            if (lane >= off) w += n;
        }
        wsum[lane] = w;
    }
    __syncthreads();
    int excl = (warp ? wsum[warp - 1] : 0) + inc - s;
    #pragma unroll
    for (int p = 0; p < PER; p++) {
        int idx = base + p;
        if (idx < N_NODES) g_offs[idx] = excl + loc[p];
    }
    if (t == 1023) g_offs[N_NODES] = excl + s;
}

__global__ void k_fill(const int* __restrict__ row, const int* __restrict__ col,
                       const float* __restrict__ ew) {
    int e = blockIdx.x * blockDim.x + threadIdx.x;
    if (e >= N_EDGES) return;
    int c = col[e];
    int p = atomicAdd(&g_cur[c], 1);
    int dst = g_offs[c] + p;
    g_srow[dst] = row[e];
    g_sew[dst]  = ew[e];
}

// ---------------- GCN aggregation + fused BN stats ----------------
__global__ void k_gcn(const float* __restrict__ hlin, const float* __restrict__ bias,
                      float* __restrict__ pre, float* __restrict__ stats)
{
    __shared__ float sS[HID], sQ[HID];
    int t = threadIdx.x;
    if (t < HID) { sS[t] = 0.f; sQ[t] = 0.f; }
    __syncthreads();
    int warp = t >> 5, lane = t & 31;
    int i = blockIdx.x * 8 + warp;
    if (i < N_NODES) {
        float di = g_deg[i];
        int s = g_offs[i], epnd = g_offs[i + 1];
        float4 acc = make_float4(0.f, 0.f, 0.f, 0.f);
        for (int idx = s; idx < epnd; idx++) {
            int r = g_srow[idx];
            float nrm = g_deg[r] * g_sew[idx] * di;
            float4 v = *(const float4*)(hlin + (size_t)r * HID + lane * 4);
            acc.x += nrm * v.x; acc.y += nrm * v.y;
            acc.z += nrm * v.z; acc.w += nrm * v.w;
        }
        float4 hs = *(const float4*)(hlin + (size_t)i * HID + lane * 4);
        float sl = di * di;
        float4 b4 = *(const float4*)(bias + lane * 4);
        float4 o;
        o.x = fmaxf(acc.x + hs.x * sl + b4.x, 0.f);
        o.y = fmaxf(acc.y + hs.y * sl + b4.y, 0.f);
        o.z = fmaxf(acc.z + hs.z * sl + b4.z, 0.f);
        o.w = fmaxf(acc.w + hs.w * sl + b4.w, 0.f);
        *(float4*)(pre + (size_t)i * HID + lane * 4) = o;
        int f = lane * 4;
        atomicAdd(&sS[f + 0], o.x); atomicAdd(&sQ[f + 0], o.x * o.x);
        atomicAdd(&sS[f + 1], o.y); atomicAdd(&sQ[f + 1], o.y * o.y);
        atomicAdd(&sS[f + 2], o.z); atomicAdd(&sQ[f + 2], o.z * o.z);
        atomicAdd(&sS[f + 3], o.w); atomicAdd(&sQ[f + 3], o.w * o.w);
    }
    __syncthreads();
    if (t < HID) {
        atomicAdd(&stats[t], sS[t]);
        atomicAdd(&stats[HID + t], sQ[t]);
    }
}

// ---------------- assignment + xp0 + A0 (fused, resident-grid barrier) ----------------
__global__ void k_pool0(const float* __restrict__ w, const float* __restrict__ bias,
                        const float* __restrict__ gum,
                        const int* __restrict__ row, const int* __restrict__ col,
                        const float* __restrict__ ew) {
    __shared__ float sW[NC0][HID];
    __shared__ float sAcc[NC0][HID];
    __shared__ float sA[NC0 * NC0];
    int t = threadIdx.x;
    for (int i = t; i < HID * NC0; i += 256) {
        int k = i / NC0, c = i % NC0;
        sW[c][k] = w[i];
        ((float*)sAcc)[i] = 0.f;
    }
    __syncthreads();
    int warp = t >> 5, lane = t & 31;
    for (int n = blockIdx.x * 8 + warp; n < N_NODES; n += gridDim.x * 8) {
        float4 xv = *(const float4*)(g_bottom + (size_t)n * HID + lane * 4);
        float best = -1e30f; int bi = 0;
        #pragma unroll
        for (int c = 0; c < NC0; c++) {
            float4 wv = *(float4*)&sW[c][lane * 4];
            float p = xv.x * wv.x + xv.y * wv.y + xv.z * wv.z + xv.w * wv.w;
            #pragma unroll
            for (int off = 16; off > 0; off >>= 1)
                p += __shfl_xor_sync(0xffffffffu, p, off);
            p += bias[c] + gum[(size_t)n * NC0 + c];
            if (p > best) { best = p; bi = c; }
        }
        if (lane == 0) g_c0[n] = bi;
        int f = lane * 4;
        atomicAdd(&sAcc[bi][f + 0], xv.x);
        atomicAdd(&sAcc[bi][f + 1], xv.y);
        atomicAdd(&sAcc[bi][f + 2], xv.z);
        atomicAdd(&sAcc[bi][f + 3], xv.w);
    }
    __syncthreads();
    for (int i = t; i < NC0 * HID; i += 256)
        atomicAdd(&g_xp0[i], ((float*)sAcc)[i]);

    // grid-wide barrier: 80 blocks, all resident on 148 SMs
    __threadfence();
    __syncthreads();
    if (t == 0) {
        atomicAdd(&g_bar0, 1);
        while (atomicAdd(&g_bar0, 0) < (int)gridDim.x) { }
    }
    __syncthreads();

    // A0 histogram phase
    if (t < NC0 * NC0) sA[t] = 0.f;
    __syncthreads();
    for (int e = blockIdx.x * blockDim.x + t; e < N_EDGES; e += gridDim.x * blockDim.x)
        atomicAdd(&sA[g_c0[row[e]] * NC0 + g_c0[col[e]]], ew[e]);
    __syncthreads();
    if (t < NC0 * NC0) atomicAdd(&g_A0[t], sA[t]);
}

// ---------------- tiny hierarchical pooling math ----------------
__device__ __forceinline__ float blockReduce128(float v, float* red) {
    int t = threadIdx.x;
    red[t] = v; __syncthreads();
    #pragma unroll
    for (int off = 64; off > 0; off >>= 1) {
        if (t < off) red[t] += red[t + off];
        __syncthreads();
    }
    float r = red[0]; __syncthreads();
    return r;
}

__global__ void k_levels(const float* __restrict__ me0_w, const float* __restrict__ me0_b,
                         const float* __restrict__ ml1_w, const float* __restrict__ ml1_b,
                         const float* __restrict__ gum1,
                         const float* __restrict__ me1_w, const float* __restrict__ me1_b)
{
    __shared__ float sA0[NC0 * NC0];
    __shared__ float sXp[NC0][HID];
    __shared__ float sM[NC0][HID];
    __shared__ float sL0[NC0][HID];
    __shared__ float sXp1[NC1][HID];
    __shared__ float sM1[NC1][HID];
    __shared__ float red[HID];
    __shared__ float sZ[NC0][NC1];
    __shared__ float sA1[NC1 * NC1];
    __shared__ int   sC1[NC0];
    int t = threadIdx.x;

    float a = (t < NC0 * NC0) ? g_A0[t] : 0.f;
    float S0 = blockReduce128(a, red);
    if (t < NC0 * NC0) sA0[t] = a / S0;
    __syncthreads();

    for (int c = 0; c < NC0; c++) {
        float v = g_xp0[c * HID + t];
        float nsq = blockReduce128(v * v, red);
        float nrm = sqrtf(nsq);
        sXp[c][t] = v / fmaxf(nrm, 1e-12f);
    }
    __syncthreads();

    for (int c = 0; c < NC0; c++) {
        float s = 0.f;
        #pragma unroll
        for (int k = 0; k < NC0; k++) s += sA0[c * NC0 + k] * sXp[k][t];
        sM[c][t] = s;
    }
    __syncthreads();

    {
        float acc[NC0];
        #pragma unroll
        for (int c = 0; c < NC0; c++) acc[c] = me0_b[t];
        for (int k = 0; k < HID; k++) {
            float w = me0_w[k * HID + t];
            #pragma unroll
            for (int c = 0; c < NC0; c++) acc[c] += sM[c][k] * w;
        }
        #pragma unroll
        for (int c = 0; c < NC0; c++) {
            float v = tanhf(acc[c]);
            sL0[c][t] = v;
            g_latent0[c * HID + t] = v;
        }
    }
    __syncthreads();

    if (t < NC0 * NC1) {
        int k = t / NC1, c = t % NC1;
        float s = ml1_b[c] + gum1[k * NC1 + c];
        for (int j = 0; j < HID; j++) s += sL0[k][j] * ml1_w[j * NC1 + c];
        sZ[k][c] = s;
    }
    __syncthreads();
    if (t < NC0) {
        float best = sZ[t][0]; int bi = 0;
        #pragma unroll
        for (int c = 1; c < NC1; c++)
            if (sZ[t][c] > best) { best = sZ[t][c]; bi = c; }
        sC1[t] = bi;
        g_c1[t] = bi;
    }
    __syncthreads();

    for (int c = 0; c < NC1; c++) {
        float v = 0.f;
        #pragma unroll
        for (int k = 0; k < NC0; k++)
            if (sC1[k] == c) v += sL0[k][t];
        float nsq = blockReduce128(v * v, red);
        float nrm = sqrtf(nsq);
        sXp1[c][t] = v / fmaxf(nrm, 1e-12f);
    }
    __syncthreads();

    if (t < NC1 * NC1) {
        int aa = t / NC1, bb = t % NC1;
        float s = 0.f;
        for (int k = 0; k < NC0; k++)
            for (int l = 0; l < NC0; l++)
                if (sC1[k] == aa && sC1[l] == bb) s += sA0[k * NC0 + l];
        sA1[t] = s;
    }
    __syncthreads();
    float a1v = (t < NC1 * NC1) ? sA1[t] : 0.f;
    float S1 = blockReduce128(a1v, red);
    if (t < NC1 * NC1) sA1[t] = a1v / S1;
    __syncthreads();

    for (int c = 0; c < NC1; c++) {
        float s = 0.f;
        #pragma unroll
        for (int k = 0; k < NC1; k++) s += sA1[c * NC1 + k] * sXp1[k][t];
        sM1[c][t] = s;
    }
    __syncthreads();
    {
        float acc[NC1];
        #pragma unroll
        for (int c = 0; c < NC1; c++) acc[c] = me1_b[t];
        for (int k = 0; k < HID; k++) {
            float w = me1_w[k * HID + t];
            #pragma unroll
            for (int c = 0; c < NC1; c++) acc[c] += sM1[c][k] * w;
        }
        #pragma unroll
        for (int c = 0; c < NC1; c++) g_latent1[c * HID + t] = tanhf(acc[c]);
    }
}

// ---------------- final bias + relu ----------------
__global__ void k_fin(float* __restrict__ out, const float* __restrict__ b) {
    int i = blockIdx.x * blockDim.x + threadIdx.x;
    if (i < N_NODES) out[i] = fmaxf(out[i] + b[0], 0.f);
}

// ---------------- host ----------------
extern "C" void kernel_launch(void* const* d_in, const int* in_sizes, int n_in,
                              void* d_out, int out_size)
{
    const float* x       = (const float*)d_in[0];
    const float* ew      = (const float*)d_in[1];
    const float* gum0    = (const float*)d_in[2];
    const float* gum1    = (const float*)d_in[3];
    const float* conv1_w = (const float*)d_in[4];
    const float* conv1_b = (const float*)d_in[5];
    const float* conv2_w = (const float*)d_in[6];
    const float* conv2_b = (const float*)d_in[7];
    const float* bn1_g   = (const float*)d_in[8];
    const float* bn1_b   = (const float*)d_in[9];
    const float* bn2_g   = (const float*)d_in[10];
    const float* bn2_b   = (const float*)d_in[11];
    const float* enc1_w  = (const float*)d_in[12];
    const float* enc1_b  = (const float*)d_in[13];
    const float* enc2_w  = (const float*)d_in[14];
    const float* enc2_b  = (const float*)d_in[15];
    const float* ml0_w   = (const float*)d_in[16];
    const float* ml0_b   = (const float*)d_in[17];
    const float* ml1_w   = (const float*)d_in[18];
    const float* ml1_b   = (const float*)d_in[19];
    const float* me0_w   = (const float*)d_in[20];
    const float* me0_b   = (const float*)d_in[21];
    const float* me1_w   = (const float*)d_in[22];
    const float* me1_b   = (const float*)d_in[23];
    const float* fc1_w   = (const float*)d_in[24];
    const float* fc1_b   = (const float*)d_in[25];
    const float* fc2_w   = (const float*)d_in[26];
    const float* fc2_b   = (const float*)d_in[27];
    const int*   ei      = (const int*)d_in[28];
    const int* row = ei;
    const int* col = ei + N_EDGES;
    float* out = (float*)d_out;

    float *p_hlin, *p_pre1, *p_pre2, *p_e1, *p_bottom;
    float *p_stats1, *p_stats2, *p_lat0, *p_lat1;
    __nv_bfloat16 *p_wh, *p_wl;
    cudaGetSymbolAddress((void**)&p_hlin,   g_hlin);
    cudaGetSymbolAddress((void**)&p_pre1,   g_pre1);
    cudaGetSymbolAddress((void**)&p_pre2,   g_pre2);
    cudaGetSymbolAddress((void**)&p_e1,     g_e1);
    cudaGetSymbolAddress((void**)&p_bottom, g_bottom);
    cudaGetSymbolAddress((void**)&p_stats1, g_stats1);
    cudaGetSymbolAddress((void**)&p_stats2, g_stats2);
    cudaGetSymbolAddress((void**)&p_lat0,   g_latent0);
    cudaGetSymbolAddress((void**)&p_lat1,   g_latent1);
    cudaGetSymbolAddress((void**)&p_wh,     g_wh);
    cudaGetSymbolAddress((void**)&p_wl,     g_wl);

    cudaFuncSetAttribute(tgemm, cudaFuncAttributeMaxDynamicSharedMemorySize, 65536);

    const int GB = (N_NODES + 63) / 64;   // 157
    dim3 g2(GB, 2), g8(GB, 8);
    const size_t SMEM = 65536;

    // side stream for edge infra, fork/join via events (capture-legal pattern)
    cudaStream_t side;
    cudaStreamCreateWithFlags(&side, cudaStreamNonBlocking);
    cudaEvent_t ev1, ev2;
    cudaEventCreateWithFlags(&ev1, cudaEventDisableTiming);
    cudaEventCreateWithFlags(&ev2, cudaEventDisableTiming);

    // #1 fused weight prep + zeroing (main)
    k_wz<<<(W_TOTAL + 255) / 256, 256>>>(conv1_w, conv2_w, enc1_w, enc2_w, fc1_w, out);
    cudaEventRecord(ev1, 0);
    cudaStreamWaitEvent(side, ev1, 0);
    // #2, #3 edge histogram + scan(+dinv) (side)
    k_count<<<(N_EDGES + 255) / 256, 256, 0, side>>>(col, ew);
    k_scan<<<1, 1024, 0, side>>>();
    // #4: conv1 GEMM (main, overlaps with edge infra)
    tgemm<<<g2, 256, SMEM>>>(x, nullptr, nullptr,
                             nullptr, nullptr, nullptr, nullptr, nullptr, nullptr,
                             nullptr, nullptr, nullptr,
                             p_wh + WO_CONV1, p_wl + WO_CONV1, nullptr, p_hlin,
                             nullptr, nullptr, N_NODES, 1, 128, 0, 0);
    // #5 CSR fill (side), then join
    k_fill<<<(N_EDGES + 255) / 256, 256, 0, side>>>(row, col, ew);
    cudaEventRecord(ev2, side);
    cudaStreamWaitEvent(0, ev2, 0);

    // conv1 aggregation
    k_gcn<<<1250, 256>>>(p_hlin, conv1_b, p_pre1, p_stats1);

    // conv2
    tgemm<<<g2, 256, SMEM>>>(p_pre1, nullptr, nullptr,
                             p_stats1, bn1_g, bn1_b, nullptr, nullptr, nullptr,
                             nullptr, nullptr, nullptr,
                             p_wh + WO_CONV2, p_wl + WO_CONV2, nullptr, p_hlin,
                             nullptr, nullptr, N_NODES, 1, 128, 0, 0);
    k_gcn<<<1250, 256>>>(p_hlin, conv2_b, p_pre2, p_stats2);

    // enc1 / enc2
    tgemm<<<g2, 256, SMEM>>>(x, p_pre1, p_pre2,
                             nullptr, nullptr, nullptr,
                             p_stats1, bn1_g, bn1_b,
                             p_stats2, bn2_g, bn2_b,
                             p_wh + WO_ENC1, p_wl + WO_ENC1, enc1_b, p_e1,
                             nullptr, nullptr, N_NODES, 3, 128, 1, 0);
    tgemm<<<g2, 256, SMEM>>>(p_e1, nullptr, nullptr,
                             nullptr, nullptr, nullptr, nullptr, nullptr, nullptr,
                             nullptr, nullptr, nullptr,
                             p_wh + WO_ENC2, p_wl + WO_ENC2, enc2_b, p_bottom,
                             nullptr, nullptr, N_NODES, 1, 128, 1, 0);

    // hierarchical pooling (assign + xp0 + A0 fused)
    k_pool0<<<80, 256>>>(ml0_w, ml0_b, gum0, row, col, ew);
    k_levels<<<1, 128>>>(me0_w, me0_b, ml1_w, ml1_b, gum1, me1_w, me1_b);

    // fc1 with fused fc2 partial-dot epilogue
    tgemm<<<g8, 256, SMEM>>>(p_bottom, p_lat0, p_lat1,
                             nullptr, nullptr, nullptr, nullptr, nullptr, nullptr,
                             nullptr, nullptr, nullptr,
                             p_wh + WO_FC1, p_wl + WO_FC1, fc1_b, nullptr,
                             fc2_w, out, N_NODES, 3, 512, 1, 1);
    k_fin<<<(N_NODES + 255) / 256, 256>>>(out, fc2_b);
}

// round 15
// speedup vs baseline: 1.0740x; 1.0740x over previous
#include <cuda_runtime.h>
#include <cuda_bf16.h>
#include <stdint.h>
#include <math.h>

#define N_NODES 10000
#define N_EDGES 320000
#define HID 128
#define NC0 10
#define NC1 5

// ---------------- device scratch ----------------
__device__ float g_deg[N_NODES];
__device__ int   g_cnt[N_NODES];
__device__ int   g_cur[N_NODES];
__device__ int   g_offs[N_NODES + 1];
__device__ int   g_srow[N_EDGES];
__device__ float g_sew[N_EDGES];
__device__ float g_hlin[N_NODES * HID];
__device__ float g_pre1[N_NODES * HID];
__device__ float g_pre2[N_NODES * HID];
__device__ float g_e1[N_NODES * HID];
__device__ float g_bottom[N_NODES * HID];
__device__ float g_stats1[2 * HID];
__device__ float g_stats2[2 * HID];
__device__ int   g_c0[N_NODES];
__device__ int   g_c1[NC0];
__device__ float g_xp0[NC0 * HID];
__device__ float g_A0[NC0 * NC0];
__device__ float g_latent0[NC0 * HID];
__device__ float g_latent1[NC1 * HID];
__device__ float g_q[(NC0 + NC1) * 512];     // Q0 rows 0..9, Q1 rows 10..14
__device__ int   g_bar0;

// pre-converted transposed weights [N][K] bf16 hi/lo
// fc1 keeps ONLY its first K=128 rows (bottom segment) — latent segments go via g_q
#define WO_CONV1 0
#define WO_CONV2 16384
#define WO_ENC1  32768
#define WO_ENC2  81920
#define WO_FC1   98304
#define W_TOTAL  163840
__device__ __align__(16) __nv_bfloat16 g_wh[W_TOTAL];
__device__ __align__(16) __nv_bfloat16 g_wl[W_TOTAL];

// ---------------- PTX wrappers ----------------
__device__ __forceinline__ uint32_t smem_u32(const void* p) {
    uint32_t a;
    asm("{ .reg .u64 t; cvta.to.shared.u64 t, %1; cvt.u32.u64 %0, t; }" : "=r"(a) : "l"(p));
    return a;
}
__device__ __forceinline__ void ldsm4(uint32_t r[4], uint32_t addr) {
    asm volatile("ldmatrix.sync.aligned.m8n8.x4.shared.b16 {%0,%1,%2,%3}, [%4];"
        : "=r"(r[0]), "=r"(r[1]), "=r"(r[2]), "=r"(r[3]) : "r"(addr));
}
__device__ __forceinline__ void mma16816(float d[4], const uint32_t a[4], const uint32_t b[2]) {
    asm volatile("mma.sync.aligned.m16n8k16.row.col.f32.bf16.bf16.f32 "
        "{%0,%1,%2,%3}, {%4,%5,%6,%7}, {%8,%9}, {%0,%1,%2,%3};"
        : "+f"(d[0]), "+f"(d[1]), "+f"(d[2]), "+f"(d[3])
        : "r"(a[0]), "r"(a[1]), "r"(a[2]), "r"(a[3]), "r"(b[0]), "r"(b[1]));
}
__device__ __forceinline__ void cp16(uint32_t d, const void* s) {
    asm volatile("cp.async.cg.shared.global [%0], [%1], 16;" :: "r"(d), "l"(s));
}
#define CP_COMMIT() asm volatile("cp.async.commit_group;" ::: "memory")
#define CP_WAIT0()  asm volatile("cp.async.wait_group 0;" ::: "memory")

// row swizzle value: rows 0..7 -> 0,4,1,5,2,6,3,7
__device__ __forceinline__ uint32_t swv(int row) {
    int r = row & 7;
    return (uint32_t)(((r & 1) << 2) | (r >> 1));
}
// smem tile: 64 rows x 256B (128 bf16); chunk = 16B
__device__ __forceinline__ uint32_t tadr(int row, int ch) {
    return (uint32_t)(row * 256) + ((uint32_t)(ch ^ (int)swv(row)) << 4);
}

// ---------------- fused weight prep + state zeroing ----------------
__global__ void k_wz(const float* __restrict__ w1, const float* __restrict__ w2,
                     const float* __restrict__ we1, const float* __restrict__ we2,
                     const float* __restrict__ wf1, float* __restrict__ out) {
    int i = blockIdx.x * blockDim.x + threadIdx.x;
    if (i == 0) g_bar0 = 0;
    if (i < N_NODES) { g_deg[i] = 0.f; g_cnt[i] = 0; g_cur[i] = 0; out[i] = 0.f; }
    if (i < 2 * HID) { g_stats1[i] = 0.f; g_stats2[i] = 0.f; }
    if (i < NC0 * HID) g_xp0[i] = 0.f;
    if (i < NC0 * NC0) g_A0[i] = 0.f;
    if (i >= W_TOTAL) return;
    const float* w; int K, Nn; int d = i;
    if (d < 16384)       { w = w1;  K = 128; Nn = 128; }
    else if (d < 32768)  { w = w2;  K = 128; Nn = 128; d -= 16384; }
    else if (d < 81920)  { w = we1; K = 384; Nn = 128; d -= 32768; }
    else if (d < 98304)  { w = we2; K = 128; Nn = 128; d -= 81920; }
    else                 { w = wf1; K = 128; Nn = 512; d -= 98304; }   // fc1: first 128 K-rows only
    int n = d / K, k = d % K;
    float v = w[(size_t)k * Nn + n];
    __nv_bfloat16 h = __float2bfloat16(v);
    float l = v - __bfloat162float(h);
    g_wh[i] = h;
    g_wl[i] = __float2bfloat16(l);
}

// ---------------- bf16x3 tensor-core GEMM, 64x64 tile, full-K staging ----------------
__global__ __launch_bounds__(256, 3)
void tgemm(const float* __restrict__ A0, const float* __restrict__ A1, const float* __restrict__ A2,
           const float* __restrict__ st0, const float* __restrict__ ga0, const float* __restrict__ be0,
           const float* __restrict__ st1, const float* __restrict__ ga1, const float* __restrict__ be1,
           const float* __restrict__ st2, const float* __restrict__ ga2, const float* __restrict__ be2,
           const __nv_bfloat16* __restrict__ Bh, const __nv_bfloat16* __restrict__ Bl,
           const float* __restrict__ bias, float* __restrict__ C,
           const float* __restrict__ w2, float* __restrict__ outAcc,
           const float* __restrict__ qtab,
           int M, int nseg, int Ncols, int doRelu, int idxmode)
{
    extern __shared__ char dsm[];
    char* sAh = dsm;                  // 16 KB: A hi, 64 x 256B
    char* sAl = dsm + 16384;          // 16 KB: A lo
    char* sBh = dsm + 32768;          // 16 KB: B hi
    char* sBl = dsm + 49152;          // 16 KB: B lo
    uint32_t uAh = smem_u32(sAh), uAl = smem_u32(sAl);
    uint32_t uBh = smem_u32(sBh), uBl = smem_u32(sBl);

    int t = threadIdx.x;
    int wid = t >> 5, lane = t & 31;
    int wm = wid >> 1, wn = wid & 1;            // 4 x 2 warps, each 16 x 32
    int m0 = blockIdx.x * 64, n0 = blockIdx.y * 64;

    int sRow = t >> 2, sPart = t & 3;
    int gm = m0 + sRow;
    bool mOK = gm < M;
    int gi = mOK ? gm : 0;
    int i1 = gi, i2 = gi;
    if (idxmode && mOK) { i1 = g_c0[gi]; i2 = g_c1[i1]; }
    const float* rp[3];
    rp[0] = A0 ? A0 + (size_t)gi * 128 : (const float*)0;
    rp[1] = A1 ? A1 + (size_t)i1 * 128 : (const float*)0;
    rp[2] = A2 ? A2 + (size_t)i2 * 128 : (const float*)0;
    const float* stp[3] = { st0, st1, st2 };
    const float* gap[3] = { ga0, ga1, ga2 };
    const float* bep[3] = { be0, be1, be2 };

    int Kfull = nseg * 128;
    const float invN = 1.0f / (float)N_NODES;

    int mid = lane >> 3, r8 = lane & 7;
    int arow = wm * 16 + (mid & 1) * 8 + r8;
    int brow = wn * 32 + (mid >> 1) * 8 + r8;
    uint32_t sva = swv(arow), svb = swv(brow);
    uint32_t aH = uAh + arow * 256, aL = uAl + arow * 256;
    uint32_t bH0 = uBh + brow * 256, bL0 = uBl + brow * 256;
    uint32_t bH1 = bH0 + 16 * 256,  bL1 = bL0 + 16 * 256;

    float d[4][4];
    #pragma unroll
    for (int a = 0; a < 4; a++)
        #pragma unroll
        for (int b = 0; b < 4; b++) d[a][b] = 0.f;

    for (int seg = 0; seg < nseg; seg++) {
        if (seg) __syncthreads();
        {
            size_t gb = (size_t)(n0 + sRow) * Kfull + (size_t)seg * 128;
            #pragma unroll
            for (int j = 0; j < 4; j++) {
                int ch = sPart + 4 * j;
                uint32_t sw = tadr(sRow, ch);
                cp16(uBh + sw, Bh + gb + ch * 8);
                cp16(uBl + sw, Bl + gb + ch * 8);
            }
            CP_COMMIT();
        }
        {
            const float* ap = rp[seg];
            const float* st = stp[seg];
            const float* ga = gap[seg];
            const float* be = bep[seg];
            #pragma unroll
            for (int j = 0; j < 4; j++) {
                int ch = sPart + 4 * j;
                int kin = ch * 8;
                float4 v0 = mOK ? *(const float4*)(ap + kin)     : make_float4(0.f, 0.f, 0.f, 0.f);
                float4 v1 = mOK ? *(const float4*)(ap + kin + 4) : make_float4(0.f, 0.f, 0.f, 0.f);
                float f[8] = { v0.x, v0.y, v0.z, v0.w, v1.x, v1.y, v1.z, v1.w };
                if (st) {
                    #pragma unroll
                    for (int jj = 0; jj < 8; jj++) {
                        int k = kin + jj;
                        float m = st[k] * invN;
                        float var = st[HID + k] * invN - m * m;
                        float sc = ga[k] * rsqrtf(var + 1e-5f);
                        f[jj] = f[jj] * sc + (be[k] - m * sc);
                    }
                }
                uint32_t hi[4], lo[4];
                #pragma unroll
                for (int q = 0; q < 4; q++) {
                    __nv_bfloat162 h = __floats2bfloat162_rn(f[q * 2], f[q * 2 + 1]);
                    __nv_bfloat162 l = __floats2bfloat162_rn(f[q * 2] - __bfloat162float(h.x),
                                                             f[q * 2 + 1] - __bfloat162float(h.y));
                    hi[q] = *(uint32_t*)&h; lo[q] = *(uint32_t*)&l;
                }
                uint32_t sw = tadr(sRow, ch);
                *(uint4*)(sAh + sw) = make_uint4(hi[0], hi[1], hi[2], hi[3]);
                *(uint4*)(sAl + sw) = make_uint4(lo[0], lo[1], lo[2], lo[3]);
            }
        }
        CP_WAIT0();
        __syncthreads();

        #pragma unroll
        for (int kk = 0; kk < 8; kk++) {
            int ach = 2 * kk + (mid >> 1);
            uint32_t aw = (uint32_t)(ach ^ (int)sva) << 4;
            uint32_t ah[4], al[4];
            ldsm4(ah, aH + aw);
            ldsm4(al, aL + aw);
            int bch = 2 * kk + (mid & 1);
            uint32_t bw = (uint32_t)(bch ^ (int)svb) << 4;
            uint32_t bh[4][2], bl[4][2], tmp[4];
            ldsm4(tmp, bH0 + bw);
            bh[0][0] = tmp[0]; bh[0][1] = tmp[1]; bh[1][0] = tmp[2]; bh[1][1] = tmp[3];
            ldsm4(tmp, bH1 + bw);
            bh[2][0] = tmp[0]; bh[2][1] = tmp[1]; bh[3][0] = tmp[2]; bh[3][1] = tmp[3];
            ldsm4(tmp, bL0 + bw);
            bl[0][0] = tmp[0]; bl[0][1] = tmp[1]; bl[1][0] = tmp[2]; bl[1][1] = tmp[3];
            ldsm4(tmp, bL1 + bw);
            bl[2][0] = tmp[0]; bl[2][1] = tmp[1]; bl[3][0] = tmp[2]; bl[3][1] = tmp[3];
            #pragma unroll
            for (int nt = 0; nt < 4; nt++) {
                mma16816(d[nt], ah, bh[nt]);
                mma16816(d[nt], ah, bl[nt]);
                mma16816(d[nt], al, bh[nt]);
            }
        }
    }

    // ---- epilogue ----
    int rq = lane >> 2, cq = (lane & 3) * 2;
    int grow0 = m0 + wm * 16 + rq;
    if (w2) {
        // per-row latent lookup rows (Q0[c0] + Q1[c1]) for fc1
        const float *qa0 = nullptr, *qa1 = nullptr, *qb0 = nullptr, *qb1 = nullptr;
        if (qtab) {
            int ra = (grow0 < M) ? grow0 : 0;
            int ca = g_c0[ra];
            qa0 = qtab + (size_t)ca * 512;
            qa1 = qtab + (size_t)(NC0 + g_c1[ca]) * 512;
            int rb = (grow0 + 8 < M) ? grow0 + 8 : 0;
            int cb = g_c0[rb];
            qb0 = qtab + (size_t)cb * 512;
            qb1 = qtab + (size_t)(NC0 + g_c1[cb]) * 512;
        }
        float p0 = 0.f, p1 = 0.f;
        #pragma unroll
        for (int nt = 0; nt < 4; nt++) {
            int gcol = n0 + wn * 32 + nt * 8 + cq;
            float2 bv = *(const float2*)(bias + gcol);
            float qx0 = 0.f, qy0 = 0.f, qx1 = 0.f, qy1 = 0.f;
            if (qtab) {
                float2 u0 = *(const float2*)(qa0 + gcol);
                float2 u1 = *(const float2*)(qa1 + gcol);
                qx0 = u0.x + u1.x; qy0 = u0.y + u1.y;
                float2 v0 = *(const float2*)(qb0 + gcol);
                float2 v1 = *(const float2*)(qb1 + gcol);
                qx1 = v0.x + v1.x; qy1 = v0.y + v1.y;
            }
            float o0x = fmaxf(d[nt][0] + bv.x + qx0, 0.f), o0y = fmaxf(d[nt][1] + bv.y + qy0, 0.f);
            float o1x = fmaxf(d[nt][2] + bv.x + qx1, 0.f), o1y = fmaxf(d[nt][3] + bv.y + qy1, 0.f);
            float2 wv = *(const float2*)(w2 + gcol);
            p0 += o0x * wv.x + o0y * wv.y;
            p1 += o1x * wv.x + o1y * wv.y;
        }
        p0 += __shfl_xor_sync(0xffffffffu, p0, 1);
        p0 += __shfl_xor_sync(0xffffffffu, p0, 2);
        p1 += __shfl_xor_sync(0xffffffffu, p1, 1);
        p1 += __shfl_xor_sync(0xffffffffu, p1, 2);
        if ((lane & 3) == 0) {
            if (grow0 < M)     atomicAdd(&outAcc[grow0], p0);
            if (grow0 + 8 < M) atomicAdd(&outAcc[grow0 + 8], p1);
        }
    } else {
        #pragma unroll
        for (int nt = 0; nt < 4; nt++) {
            int gcol = n0 + wn * 32 + nt * 8 + cq;
            float2 bv = make_float2(0.f, 0.f);
            if (bias) bv = *(const float2*)(bias + gcol);
            float2 o0 = make_float2(d[nt][0] + bv.x, d[nt][1] + bv.y);
            float2 o1 = make_float2(d[nt][2] + bv.x, d[nt][3] + bv.y);
            if (doRelu) {
                o0.x = fmaxf(o0.x, 0.f); o0.y = fmaxf(o0.y, 0.f);
                o1.x = fmaxf(o1.x, 0.f); o1.y = fmaxf(o1.y, 0.f);
            }
            if (grow0 < M)     *(float2*)(C + (size_t)grow0 * Ncols + gcol) = o0;
            if (grow0 + 8 < M) *(float2*)(C + (size_t)(grow0 + 8) * Ncols + gcol) = o1;
        }
    }
}

// ---------------- edge infra ----------------
__global__ void k_count(const int* __restrict__ col, const float* __restrict__ ew) {
    int e = blockIdx.x * blockDim.x + threadIdx.x;
    if (e >= N_EDGES) return;
    int c = col[e];
    atomicAdd(&g_cnt[c], 1);
    atomicAdd(&g_deg[c], ew[e]);
}

__global__ void k_scan() {   // shuffle scan + fused dinv
    __shared__ int wsum[32];
    const int PER = 10;
    int t = threadIdx.x;
    int lane = t & 31, warp = t >> 5;
    int base = t * PER;
    int loc[PER];
    int s = 0;
    #pragma unroll
    for (int p = 0; p < PER; p++) {
        int idx = base + p;
        int v = 0;
        if (idx < N_NODES) {
            v = g_cnt[idx];
            g_deg[idx] = rsqrtf(g_deg[idx] + 1.0f);
        }
        loc[p] = s; s += v;
    }
    int inc = s;
    #pragma unroll
    for (int off = 1; off < 32; off <<= 1) {
        int n = __shfl_up_sync(0xffffffffu, inc, off);
        if (lane >= off) inc += n;
    }
    if (lane == 31) wsum[warp] = inc;
    __syncthreads();
    if (warp == 0) {
        int w = wsum[lane];
        #pragma unroll
        for (int off = 1; off < 32; off <<= 1) {
            int n = __shfl_up_sync(0xffffffffu, w, off);
            if (lane >= off) w += n;
        }
        wsum[lane] = w;
    }
    __syncthreads();
    int excl = (warp ? wsum[warp - 1] : 0) + inc - s;
    #pragma unroll
    for (int p = 0; p < PER; p++) {
        int idx = base + p;
        if (idx < N_NODES) g_offs[idx] = excl + loc[p];
    }
    if (t == 1023) g_offs[N_NODES] = excl + s;
}

__global__ void k_fill(const int* __restrict__ row, const int* __restrict__ col,
                       const float* __restrict__ ew) {
    int e = blockIdx.x * blockDim.x + threadIdx.x;
    if (e >= N_EDGES) return;
    int c = col[e];
    int p = atomicAdd(&g_cur[c], 1);
    int dst = g_offs[c] + p;
    g_srow[dst] = row[e];
    g_sew[dst]  = ew[e];
}

// ---------------- GCN aggregation + fused BN stats ----------------
__global__ void k_gcn(const float* __restrict__ hlin, const float* __restrict__ bias,
                      float* __restrict__ pre, float* __restrict__ stats)
{
    __shared__ float sS[HID], sQ[HID];
    int t = threadIdx.x;
    if (t < HID) { sS[t] = 0.f; sQ[t] = 0.f; }
    __syncthreads();
    int warp = t >> 5, lane = t & 31;
    int i = blockIdx.x * 8 + warp;
    if (i < N_NODES) {
        float di = g_deg[i];
        int s = g_offs[i], epnd = g_offs[i + 1];
        float4 acc = make_float4(0.f, 0.f, 0.f, 0.f);
        int idx = s;
        for (; idx + 1 < epnd; idx += 2) {
            int r0 = g_srow[idx], r1 = g_srow[idx + 1];
            float n0 = g_deg[r0] * g_sew[idx] * di;
            float n1 = g_deg[r1] * g_sew[idx + 1] * di;
            float4 v0 = *(const float4*)(hlin + (size_t)r0 * HID + lane * 4);
            float4 v1 = *(const float4*)(hlin + (size_t)r1 * HID + lane * 4);
            acc.x += n0 * v0.x + n1 * v1.x;
            acc.y += n0 * v0.y + n1 * v1.y;
            acc.z += n0 * v0.z + n1 * v1.z;
            acc.w += n0 * v0.w + n1 * v1.w;
        }
        if (idx < epnd) {
            int r0 = g_srow[idx];
            float n0 = g_deg[r0] * g_sew[idx] * di;
            float4 v0 = *(const float4*)(hlin + (size_t)r0 * HID + lane * 4);
            acc.x += n0 * v0.x; acc.y += n0 * v0.y;
            acc.z += n0 * v0.z; acc.w += n0 * v0.w;
        }
        float4 hs = *(const float4*)(hlin + (size_t)i * HID + lane * 4);
        float sl = di * di;
        float4 b4 = *(const float4*)(bias + lane * 4);
        float4 o;
        o.x = fmaxf(acc.x + hs.x * sl + b4.x, 0.f);
        o.y = fmaxf(acc.y + hs.y * sl + b4.y, 0.f);
        o.z = fmaxf(acc.z + hs.z * sl + b4.z, 0.f);
        o.w = fmaxf(acc.w + hs.w * sl + b4.w, 0.f);
        *(float4*)(pre + (size_t)i * HID + lane * 4) = o;
        int f = lane * 4;
        atomicAdd(&sS[f + 0], o.x); atomicAdd(&sQ[f + 0], o.x * o.x);
        atomicAdd(&sS[f + 1], o.y); atomicAdd(&sQ[f + 1], o.y * o.y);
        atomicAdd(&sS[f + 2], o.z); atomicAdd(&sQ[f + 2], o.z * o.z);
        atomicAdd(&sS[f + 3], o.w); atomicAdd(&sQ[f + 3], o.w * o.w);
    }
    __syncthreads();
    if (t < HID) {
        atomicAdd(&stats[t], sS[t]);
        atomicAdd(&stats[HID + t], sQ[t]);
    }
}

// ---------------- assignment + xp0 + A0 (fused, resident-grid barrier) ----------------
__global__ void k_pool0(const float* __restrict__ w, const float* __restrict__ bias,
                        const float* __restrict__ gum,
                        const int* __restrict__ row, const int* __restrict__ col,
                        const float* __restrict__ ew) {
    __shared__ float sW[NC0][HID];
    __shared__ float sAcc[NC0][HID];
    __shared__ float sA[NC0 * NC0];
    int t = threadIdx.x;
    for (int i = t; i < HID * NC0; i += 256) {
        int k = i / NC0, c = i % NC0;
        sW[c][k] = w[i];
        ((float*)sAcc)[i] = 0.f;
    }
    __syncthreads();
    int warp = t >> 5, lane = t & 31;
    for (int n = blockIdx.x * 8 + warp; n < N_NODES; n += gridDim.x * 8) {
        float4 xv = *(const float4*)(g_bottom + (size_t)n * HID + lane * 4);
        float best = -1e30f; int bi = 0;
        #pragma unroll
        for (int c = 0; c < NC0; c++) {
            float4 wv = *(float4*)&sW[c][lane * 4];
            float p = xv.x * wv.x + xv.y * wv.y + xv.z * wv.z + xv.w * wv.w;
            #pragma unroll
            for (int off = 16; off > 0; off >>= 1)
                p += __shfl_xor_sync(0xffffffffu, p, off);
            p += bias[c] + gum[(size_t)n * NC0 + c];
            if (p > best) { best = p; bi = c; }
        }
        if (lane == 0) g_c0[n] = bi;
        int f = lane * 4;
        atomicAdd(&sAcc[bi][f + 0], xv.x);
        atomicAdd(&sAcc[bi][f + 1], xv.y);
        atomicAdd(&sAcc[bi][f + 2], xv.z);
        atomicAdd(&sAcc[bi][f + 3], xv.w);
    }
    __syncthreads();
    for (int i = t; i < NC0 * HID; i += 256)
        atomicAdd(&g_xp0[i], ((float*)sAcc)[i]);

    __threadfence();
    __syncthreads();
    if (t == 0) {
        atomicAdd(&g_bar0, 1);
        while (atomicAdd(&g_bar0, 0) < (int)gridDim.x) { }
    }
    __syncthreads();

    if (t < NC0 * NC0) sA[t] = 0.f;
    __syncthreads();
    for (int e = blockIdx.x * blockDim.x + t; e < N_EDGES; e += gridDim.x * blockDim.x)
        atomicAdd(&sA[g_c0[row[e]] * NC0 + g_c0[col[e]]], ew[e]);
    __syncthreads();
    if (t < NC0 * NC0) atomicAdd(&g_A0[t], sA[t]);
}

// ---------------- tiny hierarchical pooling math ----------------
__device__ __forceinline__ float blockReduce128(float v, float* red) {
    int t = threadIdx.x;
    red[t] = v; __syncthreads();
    #pragma unroll
    for (int off = 64; off > 0; off >>= 1) {
        if (t < off) red[t] += red[t + off];
        __syncthreads();
    }
    float r = red[0]; __syncthreads();
    return r;
}

__global__ void k_levels(const float* __restrict__ me0_w, const float* __restrict__ me0_b,
                         const float* __restrict__ ml1_w, const float* __restrict__ ml1_b,
                         const float* __restrict__ gum1,
                         const float* __restrict__ me1_w, const float* __restrict__ me1_b)
{
    __shared__ float sA0[NC0 * NC0];
    __shared__ float sXp[NC0][HID];
    __shared__ float sM[NC0][HID];
    __shared__ float sL0[NC0][HID];
    __shared__ float sXp1[NC1][HID];
    __shared__ float sM1[NC1][HID];
    __shared__ float red[HID];
    __shared__ float sZ[NC0][NC1];
    __shared__ float sA1[NC1 * NC1];
    __shared__ int   sC1[NC0];
    int t = threadIdx.x;

    float a = (t < NC0 * NC0) ? g_A0[t] : 0.f;
    float S0 = blockReduce128(a, red);
    if (t < NC0 * NC0) sA0[t] = a / S0;
    __syncthreads();

    for (int c = 0; c < NC0; c++) {
        float v = g_xp0[c * HID + t];
        float nsq = blockReduce128(v * v, red);
        float nrm = sqrtf(nsq);
        sXp[c][t] = v / fmaxf(nrm, 1e-12f);
    }
    __syncthreads();

    for (int c = 0; c < NC0; c++) {
        float s = 0.f;
        #pragma unroll
        for (int k = 0; k < NC0; k++) s += sA0[c * NC0 + k] * sXp[k][t];
        sM[c][t] = s;
    }
    __syncthreads();

    {
        float acc[NC0];
        #pragma unroll
        for (int c = 0; c < NC0; c++) acc[c] = me0_b[t];
        for (int k = 0; k < HID; k++) {
            float w = me0_w[k * HID + t];
            #pragma unroll
            for (int c = 0; c < NC0; c++) acc[c] += sM[c][k] * w;
        }
        #pragma unroll
        for (int c = 0; c < NC0; c++) {
            float v = tanhf(acc[c]);
            sL0[c][t] = v;
            g_latent0[c * HID + t] = v;
        }
    }
    __syncthreads();

    if (t < NC0 * NC1) {
        int k = t / NC1, c = t % NC1;
        float s = ml1_b[c] + gum1[k * NC1 + c];
        for (int j = 0; j < HID; j++) s += sL0[k][j] * ml1_w[j * NC1 + c];
        sZ[k][c] = s;
    }
    __syncthreads();
    if (t < NC0) {
        float best = sZ[t][0]; int bi = 0;
        #pragma unroll
        for (int c = 1; c < NC1; c++)
            if (sZ[t][c] > best) { best = sZ[t][c]; bi = c; }
        sC1[t] = bi;
        g_c1[t] = bi;
    }
    __syncthreads();

    for (int c = 0; c < NC1; c++) {
        float v = 0.f;
        #pragma unroll
        for (int k = 0; k < NC0; k++)
            if (sC1[k] == c) v += sL0[k][t];
        float nsq = blockReduce128(v * v, red);
        float nrm = sqrtf(nsq);
        sXp1[c][t] = v / fmaxf(nrm, 1e-12f);
    }
    __syncthreads();

    if (t < NC1 * NC1) {
        int aa = t / NC1, bb = t % NC1;
        float s = 0.f;
        for (int k = 0; k < NC0; k++)
            for (int l = 0; l < NC0; l++)
                if (sC1[k] == aa && sC1[l] == bb) s += sA0[k * NC0 + l];
        sA1[t] = s;
    }
    __syncthreads();
    float a1v = (t < NC1 * NC1) ? sA1[t] : 0.f;
    float S1 = blockReduce128(a1v, red);
    if (t < NC1 * NC1) sA1[t] = a1v / S1;
    __syncthreads();

    for (int c = 0; c < NC1; c++) {
        float s = 0.f;
        #pragma unroll
        for (int k = 0; k < NC1; k++) s += sA1[c * NC1 + k] * sXp1[k][t];
        sM1[c][t] = s;
    }
    __syncthreads();
    {
        float acc[NC1];
        #pragma unroll
        for (int c = 0; c < NC1; c++) acc[c] = me1_b[t];
        for (int k = 0; k < HID; k++) {
            float w = me1_w[k * HID + t];
            #pragma unroll
            for (int c = 0; c < NC1; c++) acc[c] += sM1[c][k] * w;
        }
        #pragma unroll
        for (int c = 0; c < NC1; c++) g_latent1[c * HID + t] = tanhf(acc[c]);
    }
}

// ---------------- Q tables: Q0 = latent0 @ fc1_w[128:256], Q1 = latent1 @ fc1_w[256:384] ----------------
// grid (15, 4), 128 threads: block (c, nb), thread t -> col nb*128+t, fp32 exact.
__global__ void k_qprep(const float* __restrict__ fc1_w) {
    int c = blockIdx.x;
    int n = blockIdx.y * 128 + threadIdx.x;
    const float* lat;
    int woff;
    if (c < NC0) { lat = g_latent0 + c * HID;         woff = 128; }
    else         { lat = g_latent1 + (c - NC0) * HID; woff = 256; }
    float acc = 0.f;
    #pragma unroll 8
    for (int k = 0; k < HID; k++)
        acc += lat[k] * fc1_w[(size_t)(woff + k) * 512 + n];
    g_q[(size_t)c * 512 + n] = acc;
}

// ---------------- final bias + relu ----------------
__global__ void k_fin(float* __restrict__ out, const float* __restrict__ b) {
    int i = blockIdx.x * blockDim.x + threadIdx.x;
    if (i < N_NODES) out[i] = fmaxf(out[i] + b[0], 0.f);
}

// ---------------- host ----------------
extern "C" void kernel_launch(void* const* d_in, const int* in_sizes, int n_in,
                              void* d_out, int out_size)
{
    const float* x       = (const float*)d_in[0];
    const float* ew      = (const float*)d_in[1];
    const float* gum0    = (const float*)d_in[2];
    const float* gum1    = (const float*)d_in[3];
    const float* conv1_w = (const float*)d_in[4];
    const float* conv1_b = (const float*)d_in[5];
    const float* conv2_w = (const float*)d_in[6];
    const float* conv2_b = (const float*)d_in[7];
    const float* bn1_g   = (const float*)d_in[8];
    const float* bn1_b   = (const float*)d_in[9];
    const float* bn2_g   = (const float*)d_in[10];
    const float* bn2_b   = (const float*)d_in[11];
    const float* enc1_w  = (const float*)d_in[12];
    const float* enc1_b  = (const float*)d_in[13];
    const float* enc2_w  = (const float*)d_in[14];
    const float* enc2_b  = (const float*)d_in[15];
    const float* ml0_w   = (const float*)d_in[16];
    const float* ml0_b   = (const float*)d_in[17];
    const float* ml1_w   = (const float*)d_in[18];
    const float* ml1_b   = (const float*)d_in[19];
    const float* me0_w   = (const float*)d_in[20];
    const float* me0_b   = (const float*)d_in[21];
    const float* me1_w   = (const float*)d_in[22];
    const float* me1_b   = (const float*)d_in[23];
    const float* fc1_w   = (const float*)d_in[24];
    const float* fc1_b   = (const float*)d_in[25];
    const float* fc2_w   = (const float*)d_in[26];
    const float* fc2_b   = (const float*)d_in[27];
    const int*   ei      = (const int*)d_in[28];
    const int* row = ei;
    const int* col = ei + N_EDGES;
    float* out = (float*)d_out;

    float *p_hlin, *p_pre1, *p_pre2, *p_e1, *p_bottom;
    float *p_stats1, *p_stats2, *p_lat0, *p_lat1, *p_q;
    __nv_bfloat16 *p_wh, *p_wl;
    cudaGetSymbolAddress((void**)&p_hlin,   g_hlin);
    cudaGetSymbolAddress((void**)&p_pre1,   g_pre1);
    cudaGetSymbolAddress((void**)&p_pre2,   g_pre2);
    cudaGetSymbolAddress((void**)&p_e1,     g_e1);
    cudaGetSymbolAddress((void**)&p_bottom, g_bottom);
    cudaGetSymbolAddress((void**)&p_stats1, g_stats1);
    cudaGetSymbolAddress((void**)&p_stats2, g_stats2);
    cudaGetSymbolAddress((void**)&p_lat0,   g_latent0);
    cudaGetSymbolAddress((void**)&p_lat1,   g_latent1);
    cudaGetSymbolAddress((void**)&p_q,      g_q);
    cudaGetSymbolAddress((void**)&p_wh,     g_wh);
    cudaGetSymbolAddress((void**)&p_wl,     g_wl);

    cudaFuncSetAttribute(tgemm, cudaFuncAttributeMaxDynamicSharedMemorySize, 65536);

    const int GB = (N_NODES + 63) / 64;   // 157
    dim3 g2(GB, 2), g8(GB, 8);
    const size_t SMEM = 65536;

    cudaStream_t side;
    cudaStreamCreateWithFlags(&side, cudaStreamNonBlocking);
    cudaEvent_t ev1, ev2;
    cudaEventCreateWithFlags(&ev1, cudaEventDisableTiming);
    cudaEventCreateWithFlags(&ev2, cudaEventDisableTiming);

    // #1 fused weight prep + zeroing (main)
    k_wz<<<(W_TOTAL + 255) / 256, 256>>>(conv1_w, conv2_w, enc1_w, enc2_w, fc1_w, out);
    cudaEventRecord(ev1, 0);
    cudaStreamWaitEvent(side, ev1, 0);
    // #2, #3 edge histogram + scan(+dinv) (side)
    k_count<<<(N_EDGES + 255) / 256, 256, 0, side>>>(col, ew);
    k_scan<<<1, 1024, 0, side>>>();
    // #4: conv1 GEMM (main, overlaps edge infra; ncu profile slot)
    tgemm<<<g2, 256, SMEM>>>(x, nullptr, nullptr,
                             nullptr, nullptr, nullptr, nullptr, nullptr, nullptr,
                             nullptr, nullptr, nullptr,
                             p_wh + WO_CONV1, p_wl + WO_CONV1, nullptr, p_hlin,
                             nullptr, nullptr, nullptr, N_NODES, 1, 128, 0, 0);
    // #5 CSR fill (side), then join
    k_fill<<<(N_EDGES + 255) / 256, 256, 0, side>>>(row, col, ew);
    cudaEventRecord(ev2, side);
    cudaStreamWaitEvent(0, ev2, 0);

    // conv1 aggregation
    k_gcn<<<1250, 256>>>(p_hlin, conv1_b, p_pre1, p_stats1);

    // conv2
    tgemm<<<g2, 256, SMEM>>>(p_pre1, nullptr, nullptr,
                             p_stats1, bn1_g, bn1_b, nullptr, nullptr, nullptr,
                             nullptr, nullptr, nullptr,
                             p_wh + WO_CONV2, p_wl + WO_CONV2, nullptr, p_hlin,
                             nullptr, nullptr, nullptr, N_NODES, 1, 128, 0, 0);
    k_gcn<<<1250, 256>>>(p_hlin, conv2_b, p_pre2, p_stats2);

    // enc1 / enc2
    tgemm<<<g2, 256, SMEM>>>(x, p_pre1, p_pre2,
                             nullptr, nullptr, nullptr,
                             p_stats1, bn1_g, bn1_b,
                             p_stats2, bn2_g, bn2_b,
                             p_wh + WO_ENC1, p_wl + WO_ENC1, enc1_b, p_e1,
                             nullptr, nullptr, nullptr, N_NODES, 3, 128, 1, 0);
    tgemm<<<g2, 256, SMEM>>>(p_e1, nullptr, nullptr,
                             nullptr, nullptr, nullptr, nullptr, nullptr, nullptr,
                             nullptr, nullptr, nullptr,
                             p_wh + WO_ENC2, p_wl + WO_ENC2, enc2_b, p_bottom,
                             nullptr, nullptr, nullptr, N_NODES, 1, 128, 1, 0);

    // hierarchical pooling (assign + xp0 + A0 fused), then tiny levels + Q tables
    k_pool0<<<80, 256>>>(ml0_w, ml0_b, gum0, row, col, ew);
    k_levels<<<1, 128>>>(me0_w, me0_b, ml1_w, ml1_b, gum1, me1_w, me1_b);
    {
        dim3 gq(NC0 + NC1, 4);
        k_qprep<<<gq, 128>>>(fc1_w);
    }

    // fc1: K=128 (bottom only) + Q-table epilogue + fused fc2 partial-dot
    tgemm<<<g8, 256, SMEM>>>(p_bottom, nullptr, nullptr,
                             nullptr, nullptr, nullptr, nullptr, nullptr, nullptr,
                             nullptr, nullptr, nullptr,
                             p_wh + WO_FC1, p_wl + WO_FC1, fc1_b, nullptr,
                             fc2_w, out, p_q, N_NODES, 1, 512, 1, 0);
    k_fin<<<(N_NODES + 255) / 256, 256>>>(out, fc2_b);
}